// round 2
// baseline (speedup 1.0000x reference)
#include <cuda_runtime.h>

#define BATCH 128
#define NWALK 64
#define LWALK 32
#define TD 108
#define PD 19
#define FDIM 128
#define MDIM 128

// scratch: walk embeddings after Wl:  [s][b][nw][128]  (8 MB)
__device__ float g_emb[2 * BATCH * NWALK * MDIM];

// ---- packed f32x2 helpers ---------------------------------------------------
__device__ __forceinline__ unsigned long long pack2(float lo, float hi) {
    unsigned long long r;
    asm("mov.b64 %0,{%1,%2};" : "=l"(r) : "f"(lo), "f"(hi));
    return r;
}
__device__ __forceinline__ void unpack2(unsigned long long v, float& lo, float& hi) {
    asm("mov.b64 {%0,%1},%2;" : "=f"(lo), "=f"(hi) : "l"(v));
}
__device__ __forceinline__ void ffma2(unsigned long long& d,
                                      unsigned long long a,
                                      unsigned long long b) {
    asm("fma.rn.f32x2 %0,%1,%2,%0;" : "+l"(d) : "l"(a), "l"(b));
}

// ---------------------------------------------------------------------------
// Kernel 1: per-(walk, sign) self-attention over L=32, D=128, fused Wl+bl.
// grid = B*NW*2 blocks, 256 threads.
// out = coef . V  with coef[m] = sum_l softmax(q k^T / sqrt(128))[l, m]
// ---------------------------------------------------------------------------
__global__ void walk_attn_kernel(
    const float* __restrict__ timef,
    const float* __restrict__ ppf,
    const float* __restrict__ pnf,
    const float* __restrict__ weightp,
    const int*   __restrict__ signp,
    const float* __restrict__ Wq, const float* __restrict__ bq,
    const float* __restrict__ Wk, const float* __restrict__ bk,
    const float* __restrict__ Wv, const float* __restrict__ bv,
    const float* __restrict__ Wl, const float* __restrict__ bl)
{
    extern __shared__ float sm[];
    float* xT       = sm;              // [128][32]   x transposed (f-major)
    float* q        = xT + 4096;       // [32][128]
    float* kk       = q + 4096;        // [32][130]   row-major, stride 130
    float* v        = kk + 4160;       // [32][128]
    float* coefpart = v + 4096;        // [8][32]
    float* coef     = coefpart + 256;  // [32]
    float* outvec   = coef + 32;       // [128]

    const int bx   = blockIdx.x;
    const int s    = bx & 1;           // 0 = positive, 1 = negative
    const int walk = bx >> 1;
    const int b    = walk >> 6;
    const int nw   = walk & 63;
    const int tid  = threadIdx.x;

    // ---- build features: x[l][f] = [pos_sel(19) | time(108) | weight(1)] ----
    const int wbase = (b * NWALK + nw) * LWALK;
    for (int id = tid; id < FDIM * LWALK; id += 256) {
        const int l = id & 31;
        const int f = id >> 5;
        const int e = wbase + l;
        float val;
        if (f < PD) {
            const int sg = signp[e];
            const bool usep = (sg > 0) != (s == 1);
            val = usep ? ppf[e * PD + f] : pnf[e * PD + f];
        } else if (f < FDIM - 1) {
            val = timef[e * TD + (f - PD)];
        } else {
            val = weightp[e];
        }
        xT[f * 32 + l] = val;
    }
    __syncthreads();

    // ---- QKV with packed f32x2: thread (j = col, rg = 16-row group) ----
    {
        const int j  = tid & 127;
        const int rg = tid >> 7;      // 0..1
        unsigned long long aq[8], ak[8], av[8];
        const unsigned long long bq2 = pack2(bq[j], bq[j]);
        const unsigned long long bk2 = pack2(bk[j], bk[j]);
        const unsigned long long bv2 = pack2(bv[j], bv[j]);
        #pragma unroll
        for (int i = 0; i < 8; i++) { aq[i] = bq2; ak[i] = bk2; av[i] = bv2; }
        const ulonglong2* xT16 = (const ulonglong2*)xT;   // [128][2 per rg per k4]
        #pragma unroll 2
        for (int f = 0; f < FDIM; f++) {
            const float wq = Wq[f * FDIM + j];
            const float wk = Wk[f * FDIM + j];
            const float wv = Wv[f * FDIM + j];
            const unsigned long long wq2 = pack2(wq, wq);
            const unsigned long long wk2 = pack2(wk, wk);
            const unsigned long long wv2 = pack2(wv, wv);
            #pragma unroll
            for (int k4 = 0; k4 < 4; k4++) {
                const ulonglong2 p = xT16[f * 8 + rg * 4 + k4];  // 4 row values
                ffma2(aq[2*k4],   p.x, wq2); ffma2(aq[2*k4+1], p.y, wq2);
                ffma2(ak[2*k4],   p.x, wk2); ffma2(ak[2*k4+1], p.y, wk2);
                ffma2(av[2*k4],   p.x, wv2); ffma2(av[2*k4+1], p.y, wv2);
            }
        }
        #pragma unroll
        for (int p = 0; p < 8; p++) {
            const int r = rg * 16 + 2 * p;
            float lo, hi;
            unpack2(aq[p], lo, hi); q[r * 128 + j] = lo; q[(r+1) * 128 + j] = hi;
            unpack2(ak[p], lo, hi); kk[r * 130 + j] = lo; kk[(r+1) * 130 + j] = hi;
            unpack2(av[p], lo, hi); v[r * 128 + j] = lo; v[(r+1) * 128 + j] = hi;
        }
    }
    __syncthreads();

    // ---- scores (packed over f) + softmax + column-sums (coef) ----
    {
        const int m = tid & 31;          // score column = lane
        const int w = tid >> 5;          // 8 warps, rows 4w..4w+3
        unsigned long long sc2[4] = {0ULL, 0ULL, 0ULL, 0ULL};
        const unsigned long long* krow = (const unsigned long long*)(kk + m * 130);
        const unsigned long long* q2   = (const unsigned long long*)q;
        #pragma unroll 4
        for (int f2 = 0; f2 < 64; f2++) {
            const unsigned long long kf = krow[f2];
            #pragma unroll
            for (int i = 0; i < 4; i++)
                ffma2(sc2[i], q2[(4 * w + i) * 64 + f2], kf);
        }
        const float scale = 0.08838834764831845f;  // 1/sqrt(128)
        float cp = 0.f;
        #pragma unroll
        for (int i = 0; i < 4; i++) {
            float lo, hi; unpack2(sc2[i], lo, hi);
            float x = (lo + hi) * scale;
            float mx = x;
            #pragma unroll
            for (int o = 16; o > 0; o >>= 1)
                mx = fmaxf(mx, __shfl_xor_sync(0xffffffffu, mx, o));
            const float e = __expf(x - mx);
            float sme = e;
            #pragma unroll
            for (int o = 16; o > 0; o >>= 1)
                sme += __shfl_xor_sync(0xffffffffu, sme, o);
            cp += e / sme;
        }
        coefpart[w * 32 + m] = cp;
    }
    __syncthreads();
    if (tid < 32) {
        float c = 0.f;
        #pragma unroll
        for (int w = 0; w < 8; w++) c += coefpart[w * 32 + tid];
        coef[tid] = c;
    }
    __syncthreads();
    if (tid < 128) {
        float o = 0.f;
        #pragma unroll 8
        for (int m = 0; m < 32; m++) o += coef[m] * v[m * 128 + tid];
        outvec[tid] = o;
    }
    __syncthreads();
    if (tid < 128) {   // fused Wl + bl
        float r = bl[tid];
        #pragma unroll 8
        for (int f = 0; f < 128; f++) r += outvec[f] * Wl[f * 128 + tid];
        g_emb[((s * BATCH + b) * NWALK + nw) * MDIM + tid] = r;
    }
}

// ---------------------------------------------------------------------------
// Kernel 2: per-(b, sign) path attention over L=64, D=128.
// grid = 2*B blocks, 512 threads.
// ---------------------------------------------------------------------------
__global__ void path_attn_kernel(
    const float* __restrict__ Wqp, const float* __restrict__ bqp,
    const float* __restrict__ Wkp, const float* __restrict__ bkp,
    const float* __restrict__ Wvp, const float* __restrict__ bvp,
    float* __restrict__ out)
{
    extern __shared__ float sm[];
    float* xT       = sm;               // [128][64]
    float* q        = xT + 8192;        // [64][128]
    float* kk       = q + 8192;         // [64][130]
    float* v        = kk + 8320;        // [64][128]
    float* coefpart = v + 8192;         // [16][64]
    float* coef     = coefpart + 1024;  // [64]

    const int bx  = blockIdx.x;         // s*128 + b
    const int s   = bx >> 7;
    const int b   = bx & 127;
    const int tid = threadIdx.x;

    const float* x = g_emb + ((size_t)(s * BATCH + b) * NWALK) * MDIM;

    for (int id = tid; id < 64 * 128; id += 512) {
        const int l = id & 63;
        const int d = id >> 6;
        xT[d * 64 + l] = x[l * 128 + d];
    }
    __syncthreads();

    // ---- QKV packed ----
    {
        const int j  = tid & 127;
        const int rg = tid >> 7;       // 0..3, rows rg*16..+15
        unsigned long long aq[8], ak[8], av[8];
        const unsigned long long bq2 = pack2(bqp[j], bqp[j]);
        const unsigned long long bk2 = pack2(bkp[j], bkp[j]);
        const unsigned long long bv2 = pack2(bvp[j], bvp[j]);
        #pragma unroll
        for (int i = 0; i < 8; i++) { aq[i] = bq2; ak[i] = bk2; av[i] = bv2; }
        const ulonglong2* xT16 = (const ulonglong2*)xT;   // [128][16 floats per rg]
        #pragma unroll 2
        for (int f = 0; f < FDIM; f++) {
            const float wq = Wqp[f * FDIM + j];
            const float wk = Wkp[f * FDIM + j];
            const float wv = Wvp[f * FDIM + j];
            const unsigned long long wq2 = pack2(wq, wq);
            const unsigned long long wk2 = pack2(wk, wk);
            const unsigned long long wv2 = pack2(wv, wv);
            #pragma unroll
            for (int k4 = 0; k4 < 4; k4++) {
                const ulonglong2 p = xT16[f * 16 + rg * 4 + k4];
                ffma2(aq[2*k4],   p.x, wq2); ffma2(aq[2*k4+1], p.y, wq2);
                ffma2(ak[2*k4],   p.x, wk2); ffma2(ak[2*k4+1], p.y, wk2);
                ffma2(av[2*k4],   p.x, wv2); ffma2(av[2*k4+1], p.y, wv2);
            }
        }
        #pragma unroll
        for (int p = 0; p < 8; p++) {
            const int r = rg * 16 + 2 * p;
            float lo, hi;
            unpack2(aq[p], lo, hi); q[r * 128 + j] = lo; q[(r+1) * 128 + j] = hi;
            unpack2(ak[p], lo, hi); kk[r * 130 + j] = lo; kk[(r+1) * 130 + j] = hi;
            unpack2(av[p], lo, hi); v[r * 128 + j] = lo; v[(r+1) * 128 + j] = hi;
        }
    }
    __syncthreads();

    // ---- scores + softmax + coef (rows of 64: 2 columns per lane) ----
    {
        const int m = tid & 31;
        const int w = tid >> 5;          // 16 warps, rows 4w..4w+3
        unsigned long long sa[4] = {0ULL,0ULL,0ULL,0ULL};
        unsigned long long sb[4] = {0ULL,0ULL,0ULL,0ULL};
        const unsigned long long* krow0 = (const unsigned long long*)(kk + m * 130);
        const unsigned long long* krow1 = (const unsigned long long*)(kk + (m + 32) * 130);
        const unsigned long long* q2    = (const unsigned long long*)q;
        #pragma unroll 4
        for (int f2 = 0; f2 < 64; f2++) {
            const unsigned long long kf0 = krow0[f2];
            const unsigned long long kf1 = krow1[f2];
            #pragma unroll
            for (int i = 0; i < 4; i++) {
                const unsigned long long qf = q2[(4 * w + i) * 64 + f2];
                ffma2(sa[i], qf, kf0);
                ffma2(sb[i], qf, kf1);
            }
        }
        const float scale = 0.08838834764831845f;
        float cp0 = 0.f, cp1 = 0.f;
        #pragma unroll
        for (int i = 0; i < 4; i++) {
            float lo, hi;
            unpack2(sa[i], lo, hi); float x0 = (lo + hi) * scale;
            unpack2(sb[i], lo, hi); float x1 = (lo + hi) * scale;
            float mx = fmaxf(x0, x1);
            #pragma unroll
            for (int o = 16; o > 0; o >>= 1)
                mx = fmaxf(mx, __shfl_xor_sync(0xffffffffu, mx, o));
            const float e0 = __expf(x0 - mx);
            const float e1 = __expf(x1 - mx);
            float sme = e0 + e1;
            #pragma unroll
            for (int o = 16; o > 0; o >>= 1)
                sme += __shfl_xor_sync(0xffffffffu, sme, o);
            const float inv = 1.f / sme;
            cp0 += e0 * inv;
            cp1 += e1 * inv;
        }
        coefpart[w * 64 + m]      = cp0;
        coefpart[w * 64 + m + 32] = cp1;
    }
    __syncthreads();
    if (tid < 64) {
        float c = 0.f;
        #pragma unroll
        for (int w = 0; w < 16; w++) c += coefpart[w * 64 + tid];
        coef[tid] = c;
    }
    __syncthreads();
    if (tid < 128) {
        float o = 0.f;
        #pragma unroll 8
        for (int m = 0; m < 64; m++) o += coef[m] * v[m * 128 + tid];
        out[(size_t)(s * BATCH + b) * MDIM + tid] = o;
    }
}

// ---------------------------------------------------------------------------
extern "C" void kernel_launch(void* const* d_in, const int* in_sizes, int n_in,
                              void* d_out, int out_size)
{
    const float* timef   = (const float*)d_in[0];
    const float* ppf     = (const float*)d_in[1];
    const float* pnf     = (const float*)d_in[2];
    const float* weightp = (const float*)d_in[3];
    const int*   signp   = (const int*)  d_in[4];
    const float* Wq  = (const float*)d_in[5];  const float* bq  = (const float*)d_in[6];
    const float* Wk  = (const float*)d_in[7];  const float* bk  = (const float*)d_in[8];
    const float* Wv  = (const float*)d_in[9];  const float* bv  = (const float*)d_in[10];
    const float* Wl  = (const float*)d_in[11]; const float* bl  = (const float*)d_in[12];
    const float* Wqp = (const float*)d_in[13]; const float* bqp = (const float*)d_in[14];
    const float* Wkp = (const float*)d_in[15]; const float* bkp = (const float*)d_in[16];
    const float* Wvp = (const float*)d_in[17]; const float* bvp = (const float*)d_in[18];
    float* out = (float*)d_out;

    const int smem1 = (4096 + 4096 + 4160 + 4096 + 256 + 32 + 128) * (int)sizeof(float);
    const int smem2 = (8192 + 8192 + 8320 + 8192 + 1024 + 64) * (int)sizeof(float);

    cudaFuncSetAttribute(walk_attn_kernel, cudaFuncAttributeMaxDynamicSharedMemorySize, smem1);
    cudaFuncSetAttribute(path_attn_kernel, cudaFuncAttributeMaxDynamicSharedMemorySize, smem2);

    walk_attn_kernel<<<BATCH * NWALK * 2, 256, smem1>>>(
        timef, ppf, pnf, weightp, signp, Wq, bq, Wk, bk, Wv, bv, Wl, bl);
    path_attn_kernel<<<2 * BATCH, 512, smem2>>>(
        Wqp, bqp, Wkp, bkp, Wvp, bvp, out);
}

// round 3
// speedup vs baseline: 1.0022x; 1.0022x over previous
#include <cuda_runtime.h>

#define BATCH 128
#define NWALK 64
#define LWALK 32
#define TD 108
#define PD 19
#define FDIM 128
#define MDIM 128

// scratch: walk embeddings after Wl:  [s][b][nw][128]  (8 MB)
__device__ float g_emb[2 * BATCH * NWALK * MDIM];

// ---- packed f32x2 helpers ---------------------------------------------------
__device__ __forceinline__ unsigned long long pack2(float lo, float hi) {
    unsigned long long r;
    asm("mov.b64 %0,{%1,%2};" : "=l"(r) : "f"(lo), "f"(hi));
    return r;
}
__device__ __forceinline__ void unpack2(unsigned long long v, float& lo, float& hi) {
    asm("mov.b64 {%0,%1},%2;" : "=f"(lo), "=f"(hi) : "l"(v));
}
__device__ __forceinline__ void ffma2(unsigned long long& d,
                                      unsigned long long a,
                                      unsigned long long b) {
    asm("fma.rn.f32x2 %0,%1,%2,%0;" : "+l"(d) : "l"(a), "l"(b));
}

// ---------------------------------------------------------------------------
// Kernel 1: per-(walk, sign) self-attention over L=32, D=128, fused Wl+bl.
// grid = B*NW*2 blocks, 256 threads.
// out = coef . V  with coef[m] = sum_l softmax(q k^T / sqrt(128))[l, m]
// ---------------------------------------------------------------------------
__global__ void walk_attn_kernel(
    const float* __restrict__ timef,
    const float* __restrict__ ppf,
    const float* __restrict__ pnf,
    const float* __restrict__ weightp,
    const int*   __restrict__ signp,
    const float* __restrict__ Wq, const float* __restrict__ bq,
    const float* __restrict__ Wk, const float* __restrict__ bk,
    const float* __restrict__ Wv, const float* __restrict__ bv,
    const float* __restrict__ Wl, const float* __restrict__ bl)
{
    extern __shared__ float sm[];
    float* xT       = sm;              // [128][32]   x transposed (f-major)
    float* q        = xT + 4096;       // [32][128]
    float* kk       = q + 4096;        // [32][130]   row-major, stride 130
    float* v        = kk + 4160;       // [32][128]
    float* coefpart = v + 4096;        // [8][32]
    float* coef     = coefpart + 256;  // [32]
    float* outvec   = coef + 32;       // [128]

    const int bx   = blockIdx.x;
    const int s    = bx & 1;           // 0 = positive, 1 = negative
    const int walk = bx >> 1;
    const int b    = walk >> 6;
    const int nw   = walk & 63;
    const int tid  = threadIdx.x;

    // ---- build features: x[l][f] = [pos_sel(19) | time(108) | weight(1)] ----
    const int wbase = (b * NWALK + nw) * LWALK;
    for (int id = tid; id < FDIM * LWALK; id += 256) {
        const int l = id & 31;
        const int f = id >> 5;
        const int e = wbase + l;
        float val;
        if (f < PD) {
            const int sg = signp[e];
            const bool usep = (sg > 0) != (s == 1);
            val = usep ? ppf[e * PD + f] : pnf[e * PD + f];
        } else if (f < FDIM - 1) {
            val = timef[e * TD + (f - PD)];
        } else {
            val = weightp[e];
        }
        xT[f * 32 + l] = val;
    }
    __syncthreads();

    // ---- QKV with packed f32x2: thread (j = col, rg = 16-row group) ----
    {
        const int j  = tid & 127;
        const int rg = tid >> 7;      // 0..1
        unsigned long long aq[8], ak[8], av[8];
        const unsigned long long bq2 = pack2(bq[j], bq[j]);
        const unsigned long long bk2 = pack2(bk[j], bk[j]);
        const unsigned long long bv2 = pack2(bv[j], bv[j]);
        #pragma unroll
        for (int i = 0; i < 8; i++) { aq[i] = bq2; ak[i] = bk2; av[i] = bv2; }
        const ulonglong2* xT16 = (const ulonglong2*)xT;   // [128][2 per rg per k4]
        #pragma unroll 2
        for (int f = 0; f < FDIM; f++) {
            const float wq = Wq[f * FDIM + j];
            const float wk = Wk[f * FDIM + j];
            const float wv = Wv[f * FDIM + j];
            const unsigned long long wq2 = pack2(wq, wq);
            const unsigned long long wk2 = pack2(wk, wk);
            const unsigned long long wv2 = pack2(wv, wv);
            #pragma unroll
            for (int k4 = 0; k4 < 4; k4++) {
                const ulonglong2 p = xT16[f * 8 + rg * 4 + k4];  // 4 row values
                ffma2(aq[2*k4],   p.x, wq2); ffma2(aq[2*k4+1], p.y, wq2);
                ffma2(ak[2*k4],   p.x, wk2); ffma2(ak[2*k4+1], p.y, wk2);
                ffma2(av[2*k4],   p.x, wv2); ffma2(av[2*k4+1], p.y, wv2);
            }
        }
        #pragma unroll
        for (int p = 0; p < 8; p++) {
            const int r = rg * 16 + 2 * p;
            float lo, hi;
            unpack2(aq[p], lo, hi); q[r * 128 + j] = lo; q[(r+1) * 128 + j] = hi;
            unpack2(ak[p], lo, hi); kk[r * 130 + j] = lo; kk[(r+1) * 130 + j] = hi;
            unpack2(av[p], lo, hi); v[r * 128 + j] = lo; v[(r+1) * 128 + j] = hi;
        }
    }
    __syncthreads();

    // ---- scores (packed over f) + softmax + column-sums (coef) ----
    {
        const int m = tid & 31;          // score column = lane
        const int w = tid >> 5;          // 8 warps, rows 4w..4w+3
        unsigned long long sc2[4] = {0ULL, 0ULL, 0ULL, 0ULL};
        const unsigned long long* krow = (const unsigned long long*)(kk + m * 130);
        const unsigned long long* q2   = (const unsigned long long*)q;
        #pragma unroll 4
        for (int f2 = 0; f2 < 64; f2++) {
            const unsigned long long kf = krow[f2];
            #pragma unroll
            for (int i = 0; i < 4; i++)
                ffma2(sc2[i], q2[(4 * w + i) * 64 + f2], kf);
        }
        const float scale = 0.08838834764831845f;  // 1/sqrt(128)
        float cp = 0.f;
        #pragma unroll
        for (int i = 0; i < 4; i++) {
            float lo, hi; unpack2(sc2[i], lo, hi);
            float x = (lo + hi) * scale;
            float mx = x;
            #pragma unroll
            for (int o = 16; o > 0; o >>= 1)
                mx = fmaxf(mx, __shfl_xor_sync(0xffffffffu, mx, o));
            const float e = __expf(x - mx);
            float sme = e;
            #pragma unroll
            for (int o = 16; o > 0; o >>= 1)
                sme += __shfl_xor_sync(0xffffffffu, sme, o);
            cp += e / sme;
        }
        coefpart[w * 32 + m] = cp;
    }
    __syncthreads();
    if (tid < 32) {
        float c = 0.f;
        #pragma unroll
        for (int w = 0; w < 8; w++) c += coefpart[w * 32 + tid];
        coef[tid] = c;
    }
    __syncthreads();
    if (tid < 128) {
        float o = 0.f;
        #pragma unroll 8
        for (int m = 0; m < 32; m++) o += coef[m] * v[m * 128 + tid];
        outvec[tid] = o;
    }
    __syncthreads();
    if (tid < 128) {   // fused Wl + bl
        float r = bl[tid];
        #pragma unroll 8
        for (int f = 0; f < 128; f++) r += outvec[f] * Wl[f * 128 + tid];
        g_emb[((s * BATCH + b) * NWALK + nw) * MDIM + tid] = r;
    }
}

// ---------------------------------------------------------------------------
// Kernel 2: per-(b, sign) path attention over L=64, D=128.
// grid = 2*B blocks, 512 threads.
// ---------------------------------------------------------------------------
__global__ void path_attn_kernel(
    const float* __restrict__ Wqp, const float* __restrict__ bqp,
    const float* __restrict__ Wkp, const float* __restrict__ bkp,
    const float* __restrict__ Wvp, const float* __restrict__ bvp,
    float* __restrict__ out)
{
    extern __shared__ float sm[];
    float* xT       = sm;               // [128][64]
    float* q        = xT + 8192;        // [64][128]
    float* kk       = q + 8192;         // [64][130]
    float* v        = kk + 8320;        // [64][128]
    float* coefpart = v + 8192;         // [16][64]
    float* coef     = coefpart + 1024;  // [64]

    const int bx  = blockIdx.x;         // s*128 + b
    const int s   = bx >> 7;
    const int b   = bx & 127;
    const int tid = threadIdx.x;

    const float* x = g_emb + ((size_t)(s * BATCH + b) * NWALK) * MDIM;

    for (int id = tid; id < 64 * 128; id += 512) {
        const int l = id & 63;
        const int d = id >> 6;
        xT[d * 64 + l] = x[l * 128 + d];
    }
    __syncthreads();

    // ---- QKV packed ----
    {
        const int j  = tid & 127;
        const int rg = tid >> 7;       // 0..3, rows rg*16..+15
        unsigned long long aq[8], ak[8], av[8];
        const unsigned long long bq2 = pack2(bqp[j], bqp[j]);
        const unsigned long long bk2 = pack2(bkp[j], bkp[j]);
        const unsigned long long bv2 = pack2(bvp[j], bvp[j]);
        #pragma unroll
        for (int i = 0; i < 8; i++) { aq[i] = bq2; ak[i] = bk2; av[i] = bv2; }
        const ulonglong2* xT16 = (const ulonglong2*)xT;   // [128][16 floats per rg]
        #pragma unroll 2
        for (int f = 0; f < FDIM; f++) {
            const float wq = Wqp[f * FDIM + j];
            const float wk = Wkp[f * FDIM + j];
            const float wv = Wvp[f * FDIM + j];
            const unsigned long long wq2 = pack2(wq, wq);
            const unsigned long long wk2 = pack2(wk, wk);
            const unsigned long long wv2 = pack2(wv, wv);
            #pragma unroll
            for (int k4 = 0; k4 < 4; k4++) {
                const ulonglong2 p = xT16[f * 16 + rg * 4 + k4];
                ffma2(aq[2*k4],   p.x, wq2); ffma2(aq[2*k4+1], p.y, wq2);
                ffma2(ak[2*k4],   p.x, wk2); ffma2(ak[2*k4+1], p.y, wk2);
                ffma2(av[2*k4],   p.x, wv2); ffma2(av[2*k4+1], p.y, wv2);
            }
        }
        #pragma unroll
        for (int p = 0; p < 8; p++) {
            const int r = rg * 16 + 2 * p;
            float lo, hi;
            unpack2(aq[p], lo, hi); q[r * 128 + j] = lo; q[(r+1) * 128 + j] = hi;
            unpack2(ak[p], lo, hi); kk[r * 130 + j] = lo; kk[(r+1) * 130 + j] = hi;
            unpack2(av[p], lo, hi); v[r * 128 + j] = lo; v[(r+1) * 128 + j] = hi;
        }
    }
    __syncthreads();

    // ---- scores + softmax + coef (rows of 64: 2 columns per lane) ----
    {
        const int m = tid & 31;
        const int w = tid >> 5;          // 16 warps, rows 4w..4w+3
        unsigned long long sa[4] = {0ULL,0ULL,0ULL,0ULL};
        unsigned long long sb[4] = {0ULL,0ULL,0ULL,0ULL};
        const unsigned long long* krow0 = (const unsigned long long*)(kk + m * 130);
        const unsigned long long* krow1 = (const unsigned long long*)(kk + (m + 32) * 130);
        const unsigned long long* q2    = (const unsigned long long*)q;
        #pragma unroll 4
        for (int f2 = 0; f2 < 64; f2++) {
            const unsigned long long kf0 = krow0[f2];
            const unsigned long long kf1 = krow1[f2];
            #pragma unroll
            for (int i = 0; i < 4; i++) {
                const unsigned long long qf = q2[(4 * w + i) * 64 + f2];
                ffma2(sa[i], qf, kf0);
                ffma2(sb[i], qf, kf1);
            }
        }
        const float scale = 0.08838834764831845f;
        float cp0 = 0.f, cp1 = 0.f;
        #pragma unroll
        for (int i = 0; i < 4; i++) {
            float lo, hi;
            unpack2(sa[i], lo, hi); float x0 = (lo + hi) * scale;
            unpack2(sb[i], lo, hi); float x1 = (lo + hi) * scale;
            float mx = fmaxf(x0, x1);
            #pragma unroll
            for (int o = 16; o > 0; o >>= 1)
                mx = fmaxf(mx, __shfl_xor_sync(0xffffffffu, mx, o));
            const float e0 = __expf(x0 - mx);
            const float e1 = __expf(x1 - mx);
            float sme = e0 + e1;
            #pragma unroll
            for (int o = 16; o > 0; o >>= 1)
                sme += __shfl_xor_sync(0xffffffffu, sme, o);
            const float inv = 1.f / sme;
            cp0 += e0 * inv;
            cp1 += e1 * inv;
        }
        coefpart[w * 64 + m]      = cp0;
        coefpart[w * 64 + m + 32] = cp1;
    }
    __syncthreads();
    if (tid < 64) {
        float c = 0.f;
        #pragma unroll
        for (int w = 0; w < 16; w++) c += coefpart[w * 64 + tid];
        coef[tid] = c;
    }
    __syncthreads();
    if (tid < 128) {
        float o = 0.f;
        #pragma unroll 8
        for (int m = 0; m < 64; m++) o += coef[m] * v[m * 128 + tid];
        out[(size_t)(s * BATCH + b) * MDIM + tid] = o;
    }
}

// ---------------------------------------------------------------------------
extern "C" void kernel_launch(void* const* d_in, const int* in_sizes, int n_in,
                              void* d_out, int out_size)
{
    const float* timef   = (const float*)d_in[0];
    const float* ppf     = (const float*)d_in[1];
    const float* pnf     = (const float*)d_in[2];
    const float* weightp = (const float*)d_in[3];
    const int*   signp   = (const int*)  d_in[4];
    const float* Wq  = (const float*)d_in[5];  const float* bq  = (const float*)d_in[6];
    const float* Wk  = (const float*)d_in[7];  const float* bk  = (const float*)d_in[8];
    const float* Wv  = (const float*)d_in[9];  const float* bv  = (const float*)d_in[10];
    const float* Wl  = (const float*)d_in[11]; const float* bl  = (const float*)d_in[12];
    const float* Wqp = (const float*)d_in[13]; const float* bqp = (const float*)d_in[14];
    const float* Wkp = (const float*)d_in[15]; const float* bkp = (const float*)d_in[16];
    const float* Wvp = (const float*)d_in[17]; const float* bvp = (const float*)d_in[18];
    float* out = (float*)d_out;

    const int smem1 = (4096 + 4096 + 4160 + 4096 + 256 + 32 + 128) * (int)sizeof(float);
    const int smem2 = (8192 + 8192 + 8320 + 8192 + 1024 + 64) * (int)sizeof(float);

    cudaFuncSetAttribute(walk_attn_kernel, cudaFuncAttributeMaxDynamicSharedMemorySize, smem1);
    cudaFuncSetAttribute(path_attn_kernel, cudaFuncAttributeMaxDynamicSharedMemorySize, smem2);

    walk_attn_kernel<<<BATCH * NWALK * 2, 256, smem1>>>(
        timef, ppf, pnf, weightp, signp, Wq, bq, Wk, bk, Wv, bv, Wl, bl);
    path_attn_kernel<<<2 * BATCH, 512, smem2>>>(
        Wqp, bqp, Wkp, bkp, Wvp, bvp, out);
}

// round 5
// speedup vs baseline: 1.2137x; 1.2110x over previous
#include <cuda_runtime.h>
#include <cuda_bf16.h>
#include <cstdint>

#define BATCH 128
#define NWALK 64
#define LWALK 32
#define TD 108
#define PD 19
#define FDIM 128
#define MDIM 128

// walk embeddings after Wl: [s][walk][128]
__device__ float g_emb[2 * BATCH * NWALK * MDIM];
// prepped weights: [3 weights][hi/lo][128 rows(j)][136 cols(f)] bf16
__device__ __align__(16) __nv_bfloat16 g_wprep[3 * 2 * 128 * 136];

// ---------------- helpers ----------------------------------------------------
__device__ __forceinline__ uint32_t smem_to_u32(const void* p) {
    uint32_t a;
    asm("{ .reg .u64 t; cvta.to.shared.u64 t, %1; cvt.u32.u64 %0, t; }" : "=r"(a) : "l"(p));
    return a;
}
__device__ __forceinline__ void ldsm4(uint32_t r[4], uint32_t addr) {
    asm volatile("ldmatrix.sync.aligned.m8n8.x4.shared.b16 {%0,%1,%2,%3}, [%4];"
                 : "=r"(r[0]), "=r"(r[1]), "=r"(r[2]), "=r"(r[3]) : "r"(addr));
}
__device__ __forceinline__ void mma16816(float d[4], const uint32_t a[4], const uint32_t b[2]) {
    asm volatile("mma.sync.aligned.m16n8k16.row.col.f32.bf16.bf16.f32 "
                 "{%0,%1,%2,%3},{%4,%5,%6,%7},{%8,%9},{%0,%1,%2,%3};"
                 : "+f"(d[0]), "+f"(d[1]), "+f"(d[2]), "+f"(d[3])
                 : "r"(a[0]), "r"(a[1]), "r"(a[2]), "r"(a[3]), "r"(b[0]), "r"(b[1]));
}
__device__ __forceinline__ uint32_t pack_bf2(float a, float b) {
    __nv_bfloat162 h = __floats2bfloat162_rn(a, b);
    uint32_t r; memcpy(&r, &h, 4); return r;
}

// SMEM layout (bytes). tiles are [128 rows][136 bf16] = 272B row stride.
#define XHI   0
#define XLO   34816
#define WHI   69632      // -> later k_hi
#define WLO   104448     // -> later k_lo
#define VS    139264     // fp32 [128][132]
#define BQS   206848
#define BKS   207360
#define BVS   207872
#define CPOFF 208384     // coefpart [8 warps][32] f32
#define CSOFF 209408     // coef [4 walks][32] f32
#define OUTS  209920     // out_s [4][128] f32
#define SMEM_W_TOTAL 211968

#define ROWB 272         // bytes per tile row

// ---------------------------------------------------------------------------
// prep kernel: W[f][j] f32 -> hi/lo bf16 tiles W^T[j][f]
// ---------------------------------------------------------------------------
__global__ void prep_w_kernel(const float* __restrict__ Wq,
                              const float* __restrict__ Wk,
                              const float* __restrict__ Wv)
{
    const int idx = blockIdx.x * 256 + threadIdx.x;   // 0 .. 49151
    const int w   = idx >> 14;
    const int rem = idx & 16383;
    const int f   = rem >> 7;
    const int j   = rem & 127;
    const float* W = (w == 0) ? Wq : (w == 1) ? Wk : Wv;
    const float val = W[f * FDIM + j];
    const __nv_bfloat16 hi = __float2bfloat16(val);
    const float lo = val - __bfloat162float(hi);
    g_wprep[(w * 2 + 0) * 17408 + j * 136 + f] = hi;
    g_wprep[(w * 2 + 1) * 17408 + j * 136 + f] = __float2bfloat16(lo);
}

// ---------------------------------------------------------------------------
// Walk kernel: 1 CTA = 4 walks of one sign. grid = 4096, 256 threads.
// ---------------------------------------------------------------------------
__global__ __launch_bounds__(256, 1)
void walk_attn_mma_kernel(
    const float* __restrict__ timef,
    const float* __restrict__ ppf,
    const float* __restrict__ pnf,
    const float* __restrict__ weightp,
    const int*   __restrict__ signp,
    const float* __restrict__ bq, const float* __restrict__ bk,
    const float* __restrict__ bv,
    const float* __restrict__ Wl, const float* __restrict__ bl)
{
    extern __shared__ char smem[];
    const uint32_t sb = smem_to_u32(smem);
    const int tid = threadIdx.x;
    const int w   = tid >> 5;          // warp 0..7, owns rows m0..m0+15
    const int l   = tid & 31;
    const int m0  = w * 16;
    const int walk_l = w >> 1;         // local walk 0..3
    const int bx  = blockIdx.x;
    const int s   = bx >> 11;
    const int g   = bx & 2047;

    float* bq_s = (float*)(smem + BQS);
    float* bk_s = (float*)(smem + BKS);
    float* bv_s = (float*)(smem + BVS);
    float* cp_s = (float*)(smem + CPOFF);
    float* coef_s = (float*)(smem + CSOFF);
    float* out_s  = (float*)(smem + OUTS);
    float* v_s    = (float*)(smem + VS);

    if (tid < 128) { bq_s[tid] = bq[tid]; bk_s[tid] = bk[tid]; bv_s[tid] = bv[tid]; }

    // ---- build X hi/lo tiles: row r = walk-local row, col f ----
    #pragma unroll 4
    for (int it = 0; it < 32; it++) {
        const int id = tid + 256 * it;       // 8192 = 128 rows x 64 f-pairs
        const int r  = id >> 6;
        const int f0 = (id & 63) * 2;
        const int wg = g * 4 + (r >> 5);
        const int e  = wg * LWALK + (r & 31);
        float x0, x1;
        {
            const int f = f0;
            if (f < PD) {
                const bool usep = (signp[e] > 0) != (s == 1);
                x0 = usep ? ppf[e * PD + f] : pnf[e * PD + f];
            } else x0 = timef[e * TD + (f - PD)];
        }
        {
            const int f = f0 + 1;
            if (f < PD) {
                const bool usep = (signp[e] > 0) != (s == 1);
                x1 = usep ? ppf[e * PD + f] : pnf[e * PD + f];
            } else if (f < FDIM - 1) x1 = timef[e * TD + (f - PD)];
            else x1 = weightp[e];
        }
        const __nv_bfloat16 h0 = __float2bfloat16(x0);
        const __nv_bfloat16 h1 = __float2bfloat16(x1);
        const uint32_t o = (uint32_t)r * ROWB + (uint32_t)f0 * 2;
        *(uint32_t*)(smem + XHI + o) = pack_bf2(__bfloat162float(h0), __bfloat162float(h1));
        *(uint32_t*)(smem + XLO + o) =
            pack_bf2(x0 - __bfloat162float(h0), x1 - __bfloat162float(h1));
    }

    // ldmatrix lane address components
    const uint32_t aRow  = (uint32_t)(m0 + (l & 15));
    const uint32_t aCol  = (uint32_t)((l >> 4) << 4);
    const uint32_t aHiB  = sb + XHI + aRow * ROWB + aCol;
    const uint32_t bRow  = (uint32_t)((l & 7) + ((l >> 4) << 3));
    const uint32_t bCol  = (uint32_t)(((l >> 3) & 1) << 4);

    uint32_t qph[16][2], qpl[16][2];   // packed q (A-frag layout), hi/lo

    // ---- QKV GEMMs: order V, Q, K ----
    for (int ci = 0; ci < 3; ci++) {
        const int c = (ci == 0) ? 2 : (ci == 1) ? 0 : 1;   // Wv, Wq, Wk
        __syncthreads();   // previous GEMM's W reads complete
        {
            const uint4* src = (const uint4*)(g_wprep + c * 2 * 17408);
            uint4* dst = (uint4*)(smem + WHI);
            #pragma unroll
            for (int i = 0; i < 17; i++) dst[tid + 256 * i] = src[tid + 256 * i];
        }
        __syncthreads();

        float acc[16][4];
        #pragma unroll
        for (int n = 0; n < 16; n++)
            #pragma unroll
            for (int i = 0; i < 4; i++) acc[n][i] = 0.f;

        #pragma unroll 2
        for (int ks = 0; ks < 8; ks++) {
            uint32_t ah[4], al[4];
            ldsm4(ah, aHiB + ks * 32);
            ldsm4(al, aHiB + (XLO - XHI) + ks * 32);
            #pragma unroll
            for (int np = 0; np < 8; np++) {
                const uint32_t ba = sb + WHI + (np * 16 + bRow) * ROWB + bCol + ks * 32;
                uint32_t bh[4], bl_[4];
                ldsm4(bh, ba);
                ldsm4(bl_, ba + (WLO - WHI));
                mma16816(acc[2*np],   ah, bh);
                mma16816(acc[2*np],   ah, bl_);
                mma16816(acc[2*np],   al, bh);
                mma16816(acc[2*np+1], ah, bh + 2);
                mma16816(acc[2*np+1], ah, bl_ + 2);
                mma16816(acc[2*np+1], al, bh + 2);
            }
        }

        if (ci == 0) {
            // V: store fp32 (no bias; added later as 32*bv)
            const int r1 = m0 + (l >> 2);
            const int c0 = (l & 3) * 2;
            #pragma unroll
            for (int nt = 0; nt < 16; nt++) {
                const int cc = nt * 8 + c0;
                v_s[r1 * 132 + cc]       = acc[nt][0];
                v_s[r1 * 132 + cc + 1]   = acc[nt][1];
                v_s[(r1+8) * 132 + cc]   = acc[nt][2];
                v_s[(r1+8) * 132 + cc+1] = acc[nt][3];
            }
        } else if (ci == 1) {
            // Q: add bias, split hi/lo, pack into A-fragment layout
            const int c0 = (l & 3) * 2;
            #pragma unroll
            for (int nt = 0; nt < 16; nt++) {
                const int cc = nt * 8 + c0;
                const float q0 = acc[nt][0] + bq_s[cc];
                const float q1 = acc[nt][1] + bq_s[cc + 1];
                const float q2 = acc[nt][2] + bq_s[cc];
                const float q3 = acc[nt][3] + bq_s[cc + 1];
                const float h0 = __bfloat162float(__float2bfloat16(q0));
                const float h1 = __bfloat162float(__float2bfloat16(q1));
                const float h2 = __bfloat162float(__float2bfloat16(q2));
                const float h3 = __bfloat162float(__float2bfloat16(q3));
                qph[nt][0] = pack_bf2(h0, h1);
                qph[nt][1] = pack_bf2(h2, h3);
                qpl[nt][0] = pack_bf2(q0 - h0, q1 - h1);
                qpl[nt][1] = pack_bf2(q2 - h2, q3 - h3);
            }
        } else {
            // K: add bias, split hi/lo, write over W region (after all reads done)
            __syncthreads();
            const int r1 = m0 + (l >> 2);
            const int c0 = (l & 3) * 2;
            #pragma unroll
            for (int nt = 0; nt < 16; nt++) {
                const int cc = nt * 8 + c0;
                const float k0 = acc[nt][0] + bk_s[cc];
                const float k1 = acc[nt][1] + bk_s[cc + 1];
                const float k2 = acc[nt][2] + bk_s[cc];
                const float k3 = acc[nt][3] + bk_s[cc + 1];
                const float h0 = __bfloat162float(__float2bfloat16(k0));
                const float h1 = __bfloat162float(__float2bfloat16(k1));
                const float h2 = __bfloat162float(__float2bfloat16(k2));
                const float h3 = __bfloat162float(__float2bfloat16(k3));
                const uint32_t o1 = (uint32_t)r1 * ROWB + (uint32_t)cc * 2;
                const uint32_t o2 = (uint32_t)(r1 + 8) * ROWB + (uint32_t)cc * 2;
                *(uint32_t*)(smem + WHI + o1) = pack_bf2(h0, h1);
                *(uint32_t*)(smem + WLO + o1) = pack_bf2(k0 - h0, k1 - h1);
                *(uint32_t*)(smem + WHI + o2) = pack_bf2(h2, h3);
                *(uint32_t*)(smem + WLO + o2) = pack_bf2(k2 - h2, k3 - h3);
            }
        }
    }
    __syncthreads();   // k tiles visible

    // ---- scores: S[16 rows x 32 walk-cols] = q . k^T, 3-way split ----
    float sacc[4][4];
    #pragma unroll
    for (int n = 0; n < 4; n++)
        #pragma unroll
        for (int i = 0; i < 4; i++) sacc[n][i] = 0.f;
    {
        const uint32_t kRow = (uint32_t)(walk_l * 32) + bRow;
        #pragma unroll
        for (int ks = 0; ks < 8; ks++) {
            const uint32_t ah[4] = {qph[2*ks][0], qph[2*ks][1], qph[2*ks+1][0], qph[2*ks+1][1]};
            const uint32_t al[4] = {qpl[2*ks][0], qpl[2*ks][1], qpl[2*ks+1][0], qpl[2*ks+1][1]};
            #pragma unroll
            for (int np = 0; np < 2; np++) {
                const uint32_t ba = sb + WHI + (kRow + np * 16) * ROWB + bCol + ks * 32;
                uint32_t bh[4], bl_[4];
                ldsm4(bh, ba);
                ldsm4(bl_, ba + (WLO - WHI));
                mma16816(sacc[2*np],   ah, bh);
                mma16816(sacc[2*np],   ah, bl_);
                mma16816(sacc[2*np],   al, bh);
                mma16816(sacc[2*np+1], ah, bh + 2);
                mma16816(sacc[2*np+1], ah, bl_ + 2);
                mma16816(sacc[2*np+1], al, bh + 2);
            }
        }
    }

    // ---- softmax rows + 16-row column sums (register/shuffle only) ----
    {
        const float scale = 0.08838834764831845f;
        float t[4][2];   // per-col partial (sum of this thread's 2 rows)
        #pragma unroll
        for (int h = 0; h < 2; h++) {    // row half: rows l/4 and l/4+8
            float x[4][2], mx = -1e30f;
            #pragma unroll
            for (int nt = 0; nt < 4; nt++) {
                x[nt][0] = sacc[nt][2*h]     * scale;
                x[nt][1] = sacc[nt][2*h + 1] * scale;
                mx = fmaxf(mx, fmaxf(x[nt][0], x[nt][1]));
            }
            mx = fmaxf(mx, __shfl_xor_sync(0xffffffffu, mx, 1));
            mx = fmaxf(mx, __shfl_xor_sync(0xffffffffu, mx, 2));
            float sum = 0.f;
            #pragma unroll
            for (int nt = 0; nt < 4; nt++) {
                x[nt][0] = __expf(x[nt][0] - mx);
                x[nt][1] = __expf(x[nt][1] - mx);
                sum += x[nt][0] + x[nt][1];
            }
            sum += __shfl_xor_sync(0xffffffffu, sum, 1);
            sum += __shfl_xor_sync(0xffffffffu, sum, 2);
            const float inv = 1.f / sum;
            #pragma unroll
            for (int nt = 0; nt < 4; nt++) {
                const float p0 = x[nt][0] * inv;
                const float p1 = x[nt][1] * inv;
                if (h == 0) { t[nt][0] = p0;        t[nt][1] = p1; }
                else        { t[nt][0] += p0;       t[nt][1] += p1; }
            }
        }
        #pragma unroll
        for (int o = 4; o <= 16; o <<= 1)
            #pragma unroll
            for (int nt = 0; nt < 4; nt++) {
                t[nt][0] += __shfl_xor_sync(0xffffffffu, t[nt][0], o);
                t[nt][1] += __shfl_xor_sync(0xffffffffu, t[nt][1], o);
            }
        if (l < 4) {
            #pragma unroll
            for (int nt = 0; nt < 4; nt++) {
                cp_s[w * 32 + nt * 8 + l * 2]     = t[nt][0];
                cp_s[w * 32 + nt * 8 + l * 2 + 1] = t[nt][1];
            }
        }
    }
    __syncthreads();

    if (tid < 128) {   // combine warp-pair partials -> coef[walk][m]
        const int wk = tid >> 5, m = tid & 31;
        coef_s[tid] = cp_s[(2 * wk) * 32 + m] + cp_s[(2 * wk + 1) * 32 + m];
    }
    __syncthreads();

    // ---- out = coef . V + 32*bv ----
    #pragma unroll
    for (int rep = 0; rep < 2; rep++) {
        const int idx = tid + rep * 256;
        const int wk = idx >> 7;
        const int j  = idx & 127;
        float o = 32.f * bv_s[j];
        #pragma unroll 8
        for (int m = 0; m < 32; m++)
            o += coef_s[wk * 32 + m] * v_s[(wk * 32 + m) * 132 + j];
        out_s[idx] = o;
    }
    __syncthreads();

    // ---- fused Wl + bl (fp32 exact) ----
    #pragma unroll
    for (int rep = 0; rep < 2; rep++) {
        const int idx = tid + rep * 256;
        const int wk = idx >> 7;
        const int m  = idx & 127;
        float acc = bl[m];
        #pragma unroll 8
        for (int f = 0; f < 128; f++)
            acc += out_s[wk * 128 + f] * Wl[f * 128 + m];
        const int wg = g * 4 + wk;
        g_emb[((size_t)(s * 8192 + wg)) * MDIM + m] = acc;
    }
}

// ---------------------------------------------------------------------------
// Path kernel (fp32, unchanged): per-(b, sign) attention over L=64, D=128.
// ---------------------------------------------------------------------------
__global__ void path_attn_kernel(
    const float* __restrict__ Wqp, const float* __restrict__ bqp,
    const float* __restrict__ Wkp, const float* __restrict__ bkp,
    const float* __restrict__ Wvp, const float* __restrict__ bvp,
    float* __restrict__ out)
{
    extern __shared__ float sm[];
    float* xT       = sm;               // [128][64]
    float* q        = xT + 8192;        // [64][128]
    float* kk       = q + 8192;         // [64][130]
    float* v        = kk + 8320;        // [64][128]
    float* coefpart = v + 8192;         // [16][64]
    float* coef     = coefpart + 1024;  // [64]

    const int bx  = blockIdx.x;
    const int s   = bx >> 7;
    const int b   = bx & 127;
    const int tid = threadIdx.x;

    const float* x = g_emb + ((size_t)(s * BATCH + b) * NWALK) * MDIM;
    for (int id = tid; id < 64 * 128; id += 512) {
        const int l = id & 63;
        const int d = id >> 6;
        xT[d * 64 + l] = x[l * 128 + d];
    }
    __syncthreads();
    {
        const int j  = tid & 127;
        const int rg = tid >> 7;
        float accq[16], acck[16], accv[16];
        const float bqj = bqp[j], bkj = bkp[j], bvj = bvp[j];
        #pragma unroll
        for (int i = 0; i < 16; i++) { accq[i] = bqj; acck[i] = bkj; accv[i] = bvj; }
        const float4* xT4 = (const float4*)xT;
        #pragma unroll 2
        for (int f = 0; f < FDIM; f++) {
            const float wq = Wqp[f * FDIM + j];
            const float wk = Wkp[f * FDIM + j];
            const float wv = Wvp[f * FDIM + j];
            #pragma unroll
            for (int k4 = 0; k4 < 4; k4++) {
                const float4 xv = xT4[f * 16 + rg * 4 + k4];
                accq[k4*4+0] += xv.x * wq; accq[k4*4+1] += xv.y * wq;
                accq[k4*4+2] += xv.z * wq; accq[k4*4+3] += xv.w * wq;
                acck[k4*4+0] += xv.x * wk; acck[k4*4+1] += xv.y * wk;
                acck[k4*4+2] += xv.z * wk; acck[k4*4+3] += xv.w * wk;
                accv[k4*4+0] += xv.x * wv; accv[k4*4+1] += xv.y * wv;
                accv[k4*4+2] += xv.z * wv; accv[k4*4+3] += xv.w * wv;
            }
        }
        #pragma unroll
        for (int i = 0; i < 16; i++) {
            const int r = rg * 16 + i;
            q[r * 128 + j] = accq[i];
            kk[r * 130 + j] = acck[i];
            v[r * 128 + j] = accv[i];
        }
    }
    __syncthreads();
    {
        const int m = tid & 31;
        const int w = tid >> 5;
        float sc0[4] = {0.f,0.f,0.f,0.f};
        float sc1[4] = {0.f,0.f,0.f,0.f};
        for (int f = 0; f < FDIM; f++) {
            const float kf0 = kk[m * 130 + f];
            const float kf1 = kk[(m + 32) * 130 + f];
            #pragma unroll
            for (int i = 0; i < 4; i++) {
                const float qf = q[(4 * w + i) * 128 + f];
                sc0[i] += qf * kf0;
                sc1[i] += qf * kf1;
            }
        }
        const float scale = 0.08838834764831845f;
        float cp0 = 0.f, cp1 = 0.f;
        #pragma unroll
        for (int i = 0; i < 4; i++) {
            float x0 = sc0[i] * scale;
            float x1 = sc1[i] * scale;
            float mx = fmaxf(x0, x1);
            #pragma unroll
            for (int o = 16; o > 0; o >>= 1)
                mx = fmaxf(mx, __shfl_xor_sync(0xffffffffu, mx, o));
            const float e0 = __expf(x0 - mx);
            const float e1 = __expf(x1 - mx);
            float sme = e0 + e1;
            #pragma unroll
            for (int o = 16; o > 0; o >>= 1)
                sme += __shfl_xor_sync(0xffffffffu, sme, o);
            const float inv = 1.f / sme;
            cp0 += e0 * inv;
            cp1 += e1 * inv;
        }
        coefpart[w * 64 + m]      = cp0;
        coefpart[w * 64 + m + 32] = cp1;
    }
    __syncthreads();
    if (tid < 64) {
        float c = 0.f;
        #pragma unroll
        for (int w = 0; w < 16; w++) c += coefpart[w * 64 + tid];
        coef[tid] = c;
    }
    __syncthreads();
    if (tid < 128) {
        float o = 0.f;
        #pragma unroll 8
        for (int m = 0; m < 64; m++) o += coef[m] * v[m * 128 + tid];
        out[(size_t)(s * BATCH + b) * MDIM + tid] = o;
    }
}

// ---------------------------------------------------------------------------
extern "C" void kernel_launch(void* const* d_in, const int* in_sizes, int n_in,
                              void* d_out, int out_size)
{
    const float* timef   = (const float*)d_in[0];
    const float* ppf     = (const float*)d_in[1];
    const float* pnf     = (const float*)d_in[2];
    const float* weightp = (const float*)d_in[3];
    const int*   signp   = (const int*)  d_in[4];
    const float* Wq  = (const float*)d_in[5];  const float* bq  = (const float*)d_in[6];
    const float* Wk  = (const float*)d_in[7];  const float* bk  = (const float*)d_in[8];
    const float* Wv  = (const float*)d_in[9];  const float* bv  = (const float*)d_in[10];
    const float* Wl  = (const float*)d_in[11]; const float* bl  = (const float*)d_in[12];
    const float* Wqp = (const float*)d_in[13]; const float* bqp = (const float*)d_in[14];
    const float* Wkp = (const float*)d_in[15]; const float* bkp = (const float*)d_in[16];
    const float* Wvp = (const float*)d_in[17]; const float* bvp = (const float*)d_in[18];
    float* out = (float*)d_out;

    const int smem2 = (8192 + 8192 + 8320 + 8192 + 1024 + 64) * (int)sizeof(float);

    cudaFuncSetAttribute(walk_attn_mma_kernel, cudaFuncAttributeMaxDynamicSharedMemorySize, SMEM_W_TOTAL);
    cudaFuncSetAttribute(path_attn_kernel, cudaFuncAttributeMaxDynamicSharedMemorySize, smem2);

    prep_w_kernel<<<192, 256>>>(Wq, Wk, Wv);
    walk_attn_mma_kernel<<<4096, 256, SMEM_W_TOTAL>>>(
        timef, ppf, pnf, weightp, signp, bq, bk, bv, Wl, bl);
    path_attn_kernel<<<256, 512, smem2>>>(
        Wqp, bqp, Wkp, bkp, Wvp, bvp, out);
}